// round 4
// baseline (speedup 1.0000x reference)
#include <cuda_runtime.h>
#include <cuda_fp16.h>
#include <cstdint>
#include <math.h>

// logits = x @ W^T + b ; softmax ; top-2 ; renormalize.
// fp16 split GEMM (hh+hl+lh) via mma.sync m16n8k16:
//  - W pre-converted to fp16 hi/lo (x64 scale) by a tiny pre-kernel
//  - B tiles: cp.async 3-stage pipeline into smem, ldmatrix
//  - A fragments: direct coalesced LDG from gmem, in-register hi/lo split
// out[0:2T) = indices (as f32), out[2T:4T) = renormalized probs.

static constexpr int D_K  = 4096;
static constexpr int NE   = 128;
static constexpr int BM   = 128;
static constexpr int KC   = 32;
static constexpr int NCH  = D_K / KC;          // 128
static constexpr int RS   = 40;                // halves per B smem row (32+8 pad)
static constexpr int BTILE = NE * RS * 2;      // 10240 B
static constexpr int STAGE = 2 * BTILE;        // hi+lo = 20480 B
static constexpr int NSTG  = 3;                // 61440 B
static constexpr int SMEM_TOTAL = 128 * 129 * 4;  // 66048 (epilogue logits; > pipeline)
static constexpr float WSCALE  = 64.0f;
static constexpr float IWSCALE = 1.0f / 64.0f;

__device__ __half2 gWhi[NE * D_K / 2];   // [e][k] row-major, 8KB/row
__device__ __half2 gWlo[NE * D_K / 2];

__global__ void __launch_bounds__(256)
convW(const float* __restrict__ W)
{
    int i = blockIdx.x * 256 + threadIdx.x;          // over NE*D_K/2
    float2 w = reinterpret_cast<const float2*>(W)[i];
    float ax = w.x * WSCALE, ay = w.y * WSCALE;
    __half hx = __float2half_rn(ax), hy = __float2half_rn(ay);
    gWhi[i] = __halves2half2(hx, hy);
    gWlo[i] = __floats2half2_rn(ax - __half2float(hx), ay - __half2float(hy));
}

__device__ __forceinline__ uint32_t smem_u32(const void* p) {
    uint32_t a;
    asm("{ .reg .u64 t; cvta.to.shared.u64 t, %1; cvt.u32.u64 %0, t; }" : "=r"(a) : "l"(p));
    return a;
}

#define LDM4(r, addr)                                                            \
    asm volatile("ldmatrix.sync.aligned.m8n8.x4.shared.b16 {%0,%1,%2,%3}, [%4];" \
                 : "=r"((r)[0]), "=r"((r)[1]), "=r"((r)[2]), "=r"((r)[3])        \
                 : "r"(addr))

#define MMA16816(c, a, b0, b1)                                               \
    asm volatile("mma.sync.aligned.m16n8k16.row.col.f32.f16.f16.f32 "        \
                 "{%0,%1,%2,%3}, {%4,%5,%6,%7}, {%8,%9}, {%0,%1,%2,%3};"     \
                 : "+f"((c)[0]), "+f"((c)[1]), "+f"((c)[2]), "+f"((c)[3])    \
                 : "r"((a)[0]), "r"((a)[1]), "r"((a)[2]), "r"((a)[3]),       \
                   "r"(b0), "r"(b1))

#define CP16(dst, src) \
    asm volatile("cp.async.cg.shared.global [%0], [%1], 16;" :: "r"(dst), "l"(src))

__device__ __forceinline__ uint32_t pack_hi(float a, float b, float& la, float& lb) {
    __half ha = __float2half_rn(a);
    __half hb = __float2half_rn(b);
    la = a - __half2float(ha);
    lb = b - __half2float(hb);
    __half2 h = __halves2half2(ha, hb);
    return *reinterpret_cast<uint32_t*>(&h);
}
__device__ __forceinline__ uint32_t pack_lo(float a, float b) {
    __half2 h = __floats2half2_rn(a, b);
    return *reinterpret_cast<uint32_t*>(&h);
}

__global__ void __launch_bounds__(256)
router_mma(const float* __restrict__ x, const float* __restrict__ bias,
           float* __restrict__ out, int T)
{
    extern __shared__ char smem[];
    const uint32_t sbase = smem_u32(smem);
    const int tid  = threadIdx.x;
    const int wid  = tid >> 5, lane = tid & 31;
    const int wm   = wid & 3;        // 4 M-groups of 32 tokens
    const int wn   = wid >> 2;       // 2 N-groups of 64 experts
    const int t0   = blockIdx.x * BM;

    float acc[2][8][4];
#pragma unroll
    for (int i = 0; i < 2; i++)
#pragma unroll
        for (int j = 0; j < 8; j++)
#pragma unroll
            for (int k = 0; k < 4; k++) acc[i][j][k] = 0.0f;

    // A fragment base: row = wm*32 + (lane>>2), col = (lane&3)*2
    const float* aBase = x + (size_t)(t0 + wm * 32 + (lane >> 2)) * D_K
                           + (lane & 3) * 2;

    // cp.async slice for B: 512 16B chunks per half-tile; this thread does
    // i = tid, tid+256 for hi and the same offsets for lo.
    const char* whiB = reinterpret_cast<const char*>(gWhi);
    const char* wloB = reinterpret_cast<const char*>(gWlo);

    auto fillB = [&](int cc, int st) {
        const uint32_t sdst = sbase + st * STAGE;
        const int kByte = cc * KC * 2;
#pragma unroll
        for (int t = 0; t < 2; t++) {
            int i   = tid + t * 256;          // 0..511
            int row = i >> 2, c16 = i & 3;
            uint32_t d = sdst + row * (RS * 2) + c16 * 16;
            const char* s = whiB + (size_t)row * (D_K * 2) + kByte + c16 * 16;
            CP16(d, s);
            const char* s2 = wloB + (size_t)row * (D_K * 2) + kByte + c16 * 16;
            CP16(d + BTILE, s2);
        }
    };

    // A raw prefetch regs: [kk][mt][q] : q -> (+0), (+8 rows), (+8 cols), (+8,+8)
    float2 araw[2][2][4];
    auto fetchA = [&](int cc) {
        const int k0 = cc * KC;
#pragma unroll
        for (int kk = 0; kk < 2; kk++)
#pragma unroll
            for (int mt = 0; mt < 2; mt++) {
                const float* p = aBase + (size_t)mt * 16 * D_K + k0 + kk * 16;
                araw[kk][mt][0] = *reinterpret_cast<const float2*>(p);
                araw[kk][mt][1] = *reinterpret_cast<const float2*>(p + 8 * D_K);
                araw[kk][mt][2] = *reinterpret_cast<const float2*>(p + 8);
                araw[kk][mt][3] = *reinterpret_cast<const float2*>(p + 8 * D_K + 8);
            }
    };

    // prologue: A chunk 0; B chunk 0 -> stage 0
    fetchA(0);
    fillB(0, 0);
    asm volatile("cp.async.commit_group;" ::: "memory");

    // ldmatrix lane offset within a 16x16 B block
    const int ltile = lane >> 3, lr = lane & 7;
    const int lmoff = ((ltile & 1) * 8 + lr) * RS + (ltile >> 1) * 8;

    for (int c = 0; c < NCH; c++) {
        // issue B for c+1 (stage (c+1)%3) — neighbors distinct mod 3, safe
        if (c + 1 < NCH) fillB(c + 1, (c + 1) % NSTG);
        asm volatile("cp.async.commit_group;" ::: "memory");

        // convert A raw (chunk c) -> fragments
        uint32_t Ah[2][2][4], Al[2][2][4];
#pragma unroll
        for (int kk = 0; kk < 2; kk++)
#pragma unroll
            for (int mt = 0; mt < 2; mt++)
#pragma unroll
                for (int q = 0; q < 4; q++) {
                    float la, lb;
                    Ah[kk][mt][q] = pack_hi(araw[kk][mt][q].x, araw[kk][mt][q].y, la, lb);
                    Al[kk][mt][q] = pack_lo(la, lb);
                }

        // prefetch A for c+1
        if (c + 1 < NCH) fetchA(c + 1);

        asm volatile("cp.async.wait_group 1;" ::: "memory");
        __syncthreads();

        const uint32_t bhBase = sbase + (c % NSTG) * STAGE;
        const uint32_t blBase = bhBase + BTILE;
#pragma unroll
        for (int kk = 0; kk < 2; kk++) {
#pragma unroll
            for (int g = 0; g < 4; g++) {   // 4 x 16 experts in this warp's 64
                uint32_t Bh[4], Bl[4];
                uint32_t off = (uint32_t)((wn * 64 + g * 16) * RS + kk * 16 + lmoff) * 2;
                LDM4(Bh, bhBase + off);
                LDM4(Bl, blBase + off);
#pragma unroll
                for (int mt = 0; mt < 2; mt++) {
#pragma unroll
                    for (int r = 0; r < 2; r++) {   // two n8 tiles per 16
                        float* a = acc[mt][g * 2 + r];
                        MMA16816(a, Ah[kk][mt], Bh[r], Bh[r + 2]);
                        MMA16816(a, Ah[kk][mt], Bl[r], Bl[r + 2]);
                        MMA16816(a, Al[kk][mt], Bh[r], Bh[r + 2]);
                    }
                }
            }
        }
        __syncthreads();   // protect stage c%3 from being refilled at c+2
    }

    // ---- epilogue: logits (pitch 129), then per-token top-2 ----
    float* lg = reinterpret_cast<float*>(smem);
    const int lr4 = lane >> 2, lc2 = (lane & 3) * 2;
#pragma unroll
    for (int mt = 0; mt < 2; mt++)
#pragma unroll
        for (int nt = 0; nt < 8; nt++)
#pragma unroll
            for (int di = 0; di < 4; di++) {
                int row = wm * 32 + mt * 16 + lr4 + (di >> 1) * 8;
                int col = wn * 64 + nt * 8 + lc2 + (di & 1);
                lg[row * 129 + col] = acc[mt][nt][di] * IWSCALE + __ldg(&bias[col]);
            }
    __syncthreads();

    if (tid < BM) {
        const float* row = &lg[tid * 129];
        float v1 = -INFINITY, v2 = -INFINITY;
        int   i1 = 0, i2 = 0;
#pragma unroll 4
        for (int e = 0; e < NE; e++) {
            float v = row[e];
            if (v > v1)      { v2 = v1; i2 = i1; v1 = v; i1 = e; }
            else if (v > v2) { v2 = v;  i2 = e; }
        }
        float ssum = 0.0f;
#pragma unroll 4
        for (int e = 0; e < NE; e++) ssum += __expf(row[e] - v1);
        float p1 = 1.0f / ssum;
        float p2 = __expf(v2 - v1) / ssum;
        float den = p1 + p2 + 1e-8f;
        int t = t0 + tid;
        out[(size_t)t * 2 + 0] = (float)i1;
        out[(size_t)t * 2 + 1] = (float)i2;
        out[(size_t)2 * T + (size_t)t * 2 + 0] = p1 / den;
        out[(size_t)2 * T + (size_t)t * 2 + 1] = p2 / den;
    }
}

extern "C" void kernel_launch(void* const* d_in, const int* in_sizes, int n_in,
                              void* d_out, int out_size)
{
    const float* x = (const float*)d_in[0];
    const float* W = (const float*)d_in[1];
    const float* b = (const float*)d_in[2];
    float* out = (float*)d_out;

    int E = in_sizes[2];            // 128
    int D = in_sizes[1] / E;        // 4096
    int T = in_sizes[0] / D;        // 16384

    static int configured = -1;
    if (configured < 0) {
        cudaFuncSetAttribute(router_mma, cudaFuncAttributeMaxDynamicSharedMemorySize,
                             SMEM_TOTAL);
        configured = 1;
    }
    convW<<<(E * D / 2) / 256, 256>>>(W);
    router_mma<<<T / BM, 256, SMEM_TOTAL>>>(x, b, out, T);
}

// round 6
// speedup vs baseline: 1.2321x; 1.2321x over previous
#include <cuda_runtime.h>
#include <cuda_fp16.h>
#include <cstdint>
#include <math.h>

// logits = x @ W^T + b ; softmax ; top-2 ; renormalize.
// fp16 split GEMM (hh+hl+lh) via mma.sync m16n8k16:
//  - W pre-converted once to fp16 hi/lo (x64 scale) by a tiny pre-kernel
//  - B tiles: cp.async (2-stage) straight into smem
//  - A tiles: LDG fp32 -> in-register hi/lo convert -> STS (2-stage)
//  - 512 threads (16 warps), warp tile 32x32, ONE __syncthreads per k-chunk
//  - ORDER: wait_group -> __syncthreads -> issue next -> compute   (fixes R5 race)
// out[0:2T) = indices (as f32), out[2T:4T) = renormalized probs.

static constexpr int D_K  = 4096;
static constexpr int NE   = 128;
static constexpr int BM   = 128;
static constexpr int KC   = 64;                // k per chunk
static constexpr int NCH  = D_K / KC;          // 64
static constexpr int RS   = 72;                // halves per smem row (64 + 8 pad)
static constexpr int HT   = 128 * RS * 2;      // 18432 B per half-tile (hi or lo)
static constexpr int STG  = 2 * HT;            // hi+lo stage = 36864 B
static constexpr int A_OFF = 0;                // A stages: 2 * STG
static constexpr int B_OFF = 2 * STG;          // B stages: 2 * STG
static constexpr int SMEM_TOTAL = 4 * STG;     // 147456 B
static constexpr float WSCALE  = 64.0f;
static constexpr float IWSCALE = 1.0f / 64.0f;

__device__ __half2 gWhi[NE * D_K / 2];   // [e][k] row-major
__device__ __half2 gWlo[NE * D_K / 2];

__global__ void __launch_bounds__(256)
convW(const float* __restrict__ W)
{
    int i = blockIdx.x * 256 + threadIdx.x;          // over NE*D_K/2
    float2 w = reinterpret_cast<const float2*>(W)[i];
    float ax = w.x * WSCALE, ay = w.y * WSCALE;
    __half hx = __float2half_rn(ax), hy = __float2half_rn(ay);
    gWhi[i] = __halves2half2(hx, hy);
    gWlo[i] = __floats2half2_rn(ax - __half2float(hx), ay - __half2float(hy));
}

__device__ __forceinline__ uint32_t smem_u32(const void* p) {
    uint32_t a;
    asm("{ .reg .u64 t; cvta.to.shared.u64 t, %1; cvt.u32.u64 %0, t; }" : "=r"(a) : "l"(p));
    return a;
}

#define LDM4(r, addr)                                                            \
    asm volatile("ldmatrix.sync.aligned.m8n8.x4.shared.b16 {%0,%1,%2,%3}, [%4];" \
                 : "=r"((r)[0]), "=r"((r)[1]), "=r"((r)[2]), "=r"((r)[3])        \
                 : "r"(addr))

#define MMA16816(c, a, b0, b1)                                               \
    asm volatile("mma.sync.aligned.m16n8k16.row.col.f32.f16.f16.f32 "        \
                 "{%0,%1,%2,%3}, {%4,%5,%6,%7}, {%8,%9}, {%0,%1,%2,%3};"     \
                 : "+f"((c)[0]), "+f"((c)[1]), "+f"((c)[2]), "+f"((c)[3])    \
                 : "r"((a)[0]), "r"((a)[1]), "r"((a)[2]), "r"((a)[3]),       \
                   "r"(b0), "r"(b1))

#define CP16(dst, src) \
    asm volatile("cp.async.cg.shared.global [%0], [%1], 16;" :: "r"(dst), "l"(src))

__device__ __forceinline__ uint32_t pack_hi(float a, float b, float& la, float& lb) {
    __half ha = __float2half_rn(a);
    __half hb = __float2half_rn(b);
    la = a - __half2float(ha);
    lb = b - __half2float(hb);
    __half2 h = __halves2half2(ha, hb);
    return *reinterpret_cast<uint32_t*>(&h);
}
__device__ __forceinline__ uint32_t pack_lo(float a, float b) {
    __half2 h = __floats2half2_rn(a, b);
    return *reinterpret_cast<uint32_t*>(&h);
}

__global__ void __launch_bounds__(512, 1)
router_mma(const float* __restrict__ x, const float* __restrict__ bias,
           float* __restrict__ out, int T)
{
    extern __shared__ char smem[];
    const uint32_t sbase = smem_u32(smem);
    const int tid  = threadIdx.x;
    const int wid  = tid >> 5, lane = tid & 31;
    const int wm   = wid & 3;        // 4 M-groups (32 tokens)
    const int wn   = wid >> 2;       // 4 N-groups (32 experts)
    const int t0   = blockIdx.x * BM;

    float acc[2][4][4];
#pragma unroll
    for (int i = 0; i < 2; i++)
#pragma unroll
        for (int j = 0; j < 4; j++)
#pragma unroll
            for (int k = 0; k < 4; k++) acc[i][j][k] = 0.0f;

    // ---- A LDG slice: 2048 float4 per 128x64 f32 tile -> 4 per thread
    float4 araw[4];
    auto fetchA = [&](int cc) {
        const int k0 = cc * KC;
#pragma unroll
        for (int j = 0; j < 4; j++) {
            int i = tid + j * 512, row = i >> 4, c4 = i & 15;
            araw[j] = *reinterpret_cast<const float4*>(
                x + (size_t)(t0 + row) * D_K + k0 + c4 * 4);
        }
    };
    auto stsA = [&](int st) {
        char* base = smem + A_OFF + st * STG;
#pragma unroll
        for (int j = 0; j < 4; j++) {
            int i = tid + j * 512, row = i >> 4, c4 = i & 15;
            uint32_t off = (uint32_t)row * (RS * 2) + c4 * 8;
            float lx, ly, lz, lw;
            uint2 hi, lo;
            hi.x = pack_hi(araw[j].x, araw[j].y, lx, ly);
            hi.y = pack_hi(araw[j].z, araw[j].w, lz, lw);
            lo.x = pack_lo(lx, ly); lo.y = pack_lo(lz, lw);
            *reinterpret_cast<uint2*>(base + off)      = hi;
            *reinterpret_cast<uint2*>(base + HT + off) = lo;
        }
    };
    const char* whiB = reinterpret_cast<const char*>(gWhi);
    const char* wloB = reinterpret_cast<const char*>(gWlo);
    auto fillB = [&](int cc, int st) {
        const uint32_t sdst = sbase + B_OFF + st * STG;
        const int kByte = cc * KC * 2;
#pragma unroll
        for (int t = 0; t < 2; t++) {
            int i   = tid + t * 512;
            int row = i >> 3, c16 = i & 7;
            uint32_t d = sdst + row * (RS * 2) + c16 * 16;
            size_t  go = (size_t)row * (D_K * 2) + kByte + c16 * 16;
            CP16(d,      whiB + go);
            CP16(d + HT, wloB + go);
        }
        asm volatile("cp.async.commit_group;" ::: "memory");
    };

    // ---- prologue: chunk 0 -> stage 0 ; prefetch A chunk 1
    fetchA(0);
    stsA(0);
    fillB(0, 0);
    fetchA(1);

    const int ltile = lane >> 3, lr = lane & 7;
    const int lmoff = ((ltile & 1) * 8 + lr) * RS + (ltile >> 1) * 8;

    for (int c = 0; c < NCH; c++) {
        const int p = c & 1;

        // my chunk-c B copies done...
        asm volatile("cp.async.wait_group 0;" ::: "memory");
        // ...and after this barrier EVERYONE's are done + stage-p A published
        // + stage p^1 readers (iter c-1) provably finished.
        __syncthreads();

        if (c + 1 < NCH) {
            fillB(c + 1, p ^ 1);
            stsA(p ^ 1);                  // araw currently holds chunk c+1
            if (c + 2 < NCH) fetchA(c + 2);
        }

        const uint32_t aH = sbase + A_OFF + p * STG;
        const uint32_t bH = sbase + B_OFF + p * STG;
#pragma unroll
        for (int kk = 0; kk < 4; kk++) {     // four k16 steps
            uint32_t Ah[2][4], Al[2][4];
#pragma unroll
            for (int mt = 0; mt < 2; mt++) {
                uint32_t off = (uint32_t)((wm * 32 + mt * 16) * RS + kk * 16 + lmoff) * 2;
                LDM4(Ah[mt], aH + off);
                LDM4(Al[mt], aH + HT + off);
            }
#pragma unroll
            for (int g = 0; g < 2; g++) {    // two 16-expert blocks
                uint32_t Bh[4], Bl[4];
                uint32_t off = (uint32_t)((wn * 32 + g * 16) * RS + kk * 16 + lmoff) * 2;
                LDM4(Bh, bH + off);
                LDM4(Bl, bH + HT + off);
#pragma unroll
                for (int mt = 0; mt < 2; mt++)
#pragma unroll
                    for (int r = 0; r < 2; r++) {
                        float* a = acc[mt][g * 2 + r];
                        MMA16816(a, Ah[mt], Bh[r], Bh[r + 2]);
                        MMA16816(a, Ah[mt], Bl[r], Bl[r + 2]);
                        MMA16816(a, Al[mt], Bh[r], Bh[r + 2]);
                    }
            }
        }
    }

    // ---- epilogue: logits (pitch 129), then per-token top-2 ----
    __syncthreads();
    float* lg = reinterpret_cast<float*>(smem);
    const int lr4 = lane >> 2, lc2 = (lane & 3) * 2;
#pragma unroll
    for (int mt = 0; mt < 2; mt++)
#pragma unroll
        for (int nt = 0; nt < 4; nt++)
#pragma unroll
            for (int di = 0; di < 4; di++) {
                int row = wm * 32 + mt * 16 + lr4 + (di >> 1) * 8;
                int col = wn * 32 + nt * 8 + lc2 + (di & 1);
                lg[row * 129 + col] = acc[mt][nt][di] * IWSCALE + __ldg(&bias[col]);
            }
    __syncthreads();

    if (tid < BM) {
        const float* row = &lg[tid * 129];
        float v1 = -INFINITY, v2 = -INFINITY;
        int   i1 = 0, i2 = 0;
#pragma unroll 4
        for (int e = 0; e < NE; e++) {
            float v = row[e];
            if (v > v1)      { v2 = v1; i2 = i1; v1 = v; i1 = e; }
            else if (v > v2) { v2 = v;  i2 = e; }
        }
        float ssum = 0.0f;
#pragma unroll 4
        for (int e = 0; e < NE; e++) ssum += __expf(row[e] - v1);
        float p1 = 1.0f / ssum;
        float p2 = __expf(v2 - v1) / ssum;
        float den = p1 + p2 + 1e-8f;
        int t = t0 + tid;
        out[(size_t)t * 2 + 0] = (float)i1;
        out[(size_t)t * 2 + 1] = (float)i2;
        out[(size_t)2 * T + (size_t)t * 2 + 0] = p1 / den;
        out[(size_t)2 * T + (size_t)t * 2 + 1] = p2 / den;
    }
}

extern "C" void kernel_launch(void* const* d_in, const int* in_sizes, int n_in,
                              void* d_out, int out_size)
{
    const float* x = (const float*)d_in[0];
    const float* W = (const float*)d_in[1];
    const float* b = (const float*)d_in[2];
    float* out = (float*)d_out;

    int E = in_sizes[2];            // 128
    int D = in_sizes[1] / E;        // 4096
    int T = in_sizes[0] / D;        // 16384

    static int configured = -1;
    if (configured < 0) {
        cudaFuncSetAttribute(router_mma, cudaFuncAttributeMaxDynamicSharedMemorySize,
                             SMEM_TOTAL);
        configured = 1;
    }
    convW<<<(E * D / 2) / 256, 256>>>(W);
    router_mma<<<T / BM, 512, SMEM_TOTAL>>>(x, b, out, T);
}